// round 1
// baseline (speedup 1.0000x reference)
#include <cuda_runtime.h>
#include <cuda_bf16.h>
#include <math.h>

// ---------------------------------------------------------------------------
// BlockwiseEarlyExitMamba: only feat[:, 31, :] feeds the classifier and the
// whole network is causal, so we process only the first 32 tokens per batch.
// B=16, T=32 (effective), D_MODEL=256, D_INNER=512, D_STATE=16, DT_RANK=16,
// DCONV=4, L=4.  N_TOK = 16*32 = 512 token rows.
// ---------------------------------------------------------------------------

#define NB      16
#define TT      32
#define NTOK    (NB*TT)      // 512
#define DM      256
#define DI      512
#define DS      16
#define DR      16
#define NL      4

// scratch (device globals; no allocation allowed)
__device__ float g_feat[NTOK*DM];
__device__ float g_xz  [NTOK*2*DI];
__device__ float g_xc  [NTOK*DI];
__device__ float g_dbl [NTOK*48];
__device__ float g_dt  [NTOK*DI];
__device__ float g_y   [NTOK*DI];
__device__ float g_out [NTOK*DM];

// ---------------------------------------------------------------------------
// Kernel 0: tokenize/fuse/LN -> feat (512 x 256). One block per token.
// ---------------------------------------------------------------------------
__global__ void featurize(const float* __restrict__ x,
                          const float* __restrict__ ep,  const float* __restrict__ ef,
                          const float* __restrict__ ed,
                          const float* __restrict__ plw, const float* __restrict__ plb,
                          const float* __restrict__ piw, const float* __restrict__ pib,
                          const float* __restrict__ fw,  const float* __restrict__ fb,
                          const float* __restrict__ tg,  const float* __restrict__ tb,
                          float* __restrict__ feat)
{
    __shared__ float cat[136];
    __shared__ float red[DM];
    int tok = blockIdx.x;
    int b = tok >> 5, tl = tok & 31;
    const float* xr = x + (b*1024 + tl)*5;   // full seq stride is 1024
    int d = threadIdx.x;
    if (d < 136) {
        float v;
        if (d < 32)       { int p = (int)xr[0]; p = min(max(p,0),255); v = ep[p*32 + d]; }
        else if (d < 64)  { v = xr[1]*plw[d-32] + plb[d-32]; }
        else if (d < 96)  { int f = (int)xr[2]; f = min(max(f,0),63);  v = ef[f*32 + (d-64)]; }
        else if (d < 128) { v = xr[3]*piw[d-96] + pib[d-96]; }
        else              { int dd = (int)xr[4]; dd = min(max(dd,0),1); v = ed[dd*8 + (d-128)]; }
        cat[d] = v;
    }
    __syncthreads();
    float acc = fb[d];
    const float* wrow = fw + d*136;
    #pragma unroll 8
    for (int j = 0; j < 136; j++) acc += cat[j]*wrow[j];
    // LayerNorm over 256
    red[d] = acc; __syncthreads();
    for (int off = 128; off; off >>= 1) { if (d < off) red[d] += red[d+off]; __syncthreads(); }
    float mean = red[0] * (1.f/DM); __syncthreads();
    float dv = acc - mean; red[d] = dv*dv; __syncthreads();
    for (int off = 128; off; off >>= 1) { if (d < off) red[d] += red[d+off]; __syncthreads(); }
    float var = red[0] * (1.f/DM);
    feat[tok*DM + d] = dv * rsqrtf(var + 1e-5f) * tg[d] + tb[d];
}

// ---------------------------------------------------------------------------
// Generic C[M,N] = A[M,K] @ B[N,K]^T ; dims must be multiples of 32/64/32.
// BM=32, BN=64, BK=32, 256 threads, 2x4 microtile per thread.
// ---------------------------------------------------------------------------
__global__ void gemm_tn(const float* __restrict__ A, const float* __restrict__ B,
                        float* __restrict__ C, int M, int N, int K)
{
    __shared__ float As[32][33];
    __shared__ float Bs[32][65];
    int bm = blockIdx.y*32, bn = blockIdx.x*64;
    int tid = threadIdx.x;
    int ty = tid >> 4, tx = tid & 15;
    float acc[2][4] = {};
    for (int k0 = 0; k0 < K; k0 += 32) {
        #pragma unroll
        for (int i = tid; i < 32*32; i += 256) {
            int m = i >> 5, k = i & 31;
            As[k][m] = A[(bm+m)*K + k0 + k];
        }
        #pragma unroll
        for (int i = tid; i < 64*32; i += 256) {
            int n = i >> 5, k = i & 31;
            Bs[k][n] = B[(bn+n)*K + k0 + k];
        }
        __syncthreads();
        #pragma unroll
        for (int k = 0; k < 32; k++) {
            float a0 = As[k][ty*2], a1 = As[k][ty*2+1];
            #pragma unroll
            for (int j = 0; j < 4; j++) {
                float bv = Bs[k][tx*4 + j];
                acc[0][j] += a0*bv;
                acc[1][j] += a1*bv;
            }
        }
        __syncthreads();
    }
    #pragma unroll
    for (int r = 0; r < 2; r++)
        #pragma unroll
        for (int j = 0; j < 4; j++)
            C[(bm + ty*2 + r)*N + bn + tx*4 + j] = acc[r][j];
}

// ---------------------------------------------------------------------------
// Fused: causal depthwise conv(4)+SiLU -> xc ;  xc @ x_proj^T -> dbl(48) ;
// softplus(dtr @ dt_w^T + dt_b) -> dt.   One block (512 thr) per token.
// ---------------------------------------------------------------------------
__global__ void fused_mid(const float* __restrict__ xz,
                          const float* __restrict__ cw, const float* __restrict__ cb,
                          const float* __restrict__ xpw,
                          const float* __restrict__ dtw, const float* __restrict__ dtb,
                          float* __restrict__ xc, float* __restrict__ dbl,
                          float* __restrict__ dt)
{
    __shared__ float xcs[DI];
    __shared__ float dbls[48];
    int tok = blockIdx.x;
    int tl  = tok & 31;
    int d   = threadIdx.x;

    float acc = cb[d];
    #pragma unroll
    for (int k = 0; k < 4; k++) {
        int tt = tl - 3 + k;
        if (tt >= 0) acc += cw[d*4 + k] * xz[(tok - 3 + k)*(2*DI) + d];
    }
    float s = acc / (1.f + __expf(-acc));   // SiLU
    xcs[d] = s;
    xc[tok*DI + d] = s;
    __syncthreads();

    int warp = d >> 5, lane = d & 31;
    #pragma unroll
    for (int i = 0; i < 3; i++) {
        int o = warp*3 + i;                 // 16 warps * 3 = 48 outputs
        const float* wr = xpw + o*DI;
        float p = 0.f;
        for (int j = lane; j < DI; j += 32) p += xcs[j]*wr[j];
        #pragma unroll
        for (int off = 16; off; off >>= 1) p += __shfl_down_sync(0xffffffffu, p, off);
        if (lane == 0) { dbls[o] = p; dbl[tok*48 + o] = p; }
    }
    __syncthreads();

    float v = dtb[d];
    const float* dwr = dtw + d*DR;
    #pragma unroll
    for (int r = 0; r < DR; r++) v += dbls[r]*dwr[r];
    dt[tok*DI + d] = (v > 20.f) ? v : log1pf(__expf(v));   // softplus
}

// ---------------------------------------------------------------------------
// Selective scan: one thread per (batch, d_inner) channel; 16-state in regs.
// Fuses y = (scan + D*xc) * silu(z).
// ---------------------------------------------------------------------------
__global__ void scan_kernel(const float* __restrict__ dt, const float* __restrict__ xc,
                            const float* __restrict__ xz, const float* __restrict__ dbl,
                            const float* __restrict__ A_log, const float* __restrict__ Dp,
                            float* __restrict__ y)
{
    int gid = blockIdx.x*blockDim.x + threadIdx.x;   // 8192 threads
    int b = gid >> 9, d = gid & (DI-1);
    float A[DS], h[DS];
    #pragma unroll
    for (int n = 0; n < DS; n++) { A[n] = -expf(A_log[d*DS + n]); h[n] = 0.f; }
    float Dd = Dp[d];
    for (int t = 0; t < TT; t++) {
        int base = b*TT + t;
        float dtv = dt[base*DI + d];
        float xv  = xc[base*DI + d];
        float zv  = xz[base*(2*DI) + DI + d];
        const float* Bt = dbl + base*48 + 16;
        const float* Ct = dbl + base*48 + 32;
        float accv = 0.f;
        float dx = dtv*xv;
        #pragma unroll
        for (int n = 0; n < DS; n++) {
            h[n] = __expf(dtv*A[n])*h[n] + dx*Bt[n];
            accv += h[n]*Ct[n];
        }
        float sz = zv / (1.f + __expf(-zv));
        y[base*DI + d] = (accv + Dd*xv) * sz;
    }
}

// ---------------------------------------------------------------------------
// residual add + LayerNorm, writes back into feat. One block per token.
// ---------------------------------------------------------------------------
__global__ void add_ln(const float* __restrict__ yo, float* __restrict__ feat,
                       const float* __restrict__ g, const float* __restrict__ b)
{
    __shared__ float red[DM];
    int tok = blockIdx.x, d = threadIdx.x;
    float v = yo[tok*DM + d] + feat[tok*DM + d];
    red[d] = v; __syncthreads();
    for (int off = 128; off; off >>= 1) { if (d < off) red[d] += red[d+off]; __syncthreads(); }
    float mean = red[0] * (1.f/DM); __syncthreads();
    float dv = v - mean; red[d] = dv*dv; __syncthreads();
    for (int off = 128; off; off >>= 1) { if (d < off) red[d] += red[d+off]; __syncthreads(); }
    float var = red[0] * (1.f/DM);
    feat[tok*DM + d] = dv * rsqrtf(var + 1e-5f) * g[d] + b[d];
}

// ---------------------------------------------------------------------------
// Classifier on token 31 of each batch.
// ---------------------------------------------------------------------------
__global__ void classifier(const float* __restrict__ feat,
                           const float* __restrict__ w1, const float* __restrict__ b1,
                           const float* __restrict__ w2, const float* __restrict__ b2,
                           float* __restrict__ out)
{
    __shared__ float hs[128];
    int b = blockIdx.x, j = threadIdx.x;
    const float* fr = feat + (b*TT + 31)*DM;
    float acc = b1[j];
    const float* wr = w1 + j*DM;
    #pragma unroll 8
    for (int d = 0; d < DM; d++) acc += fr[d]*wr[d];
    hs[j] = fmaxf(acc, 0.f);
    __syncthreads();
    if (j < 2) {
        float o = b2[j];
        const float* w2r = w2 + j*128;
        #pragma unroll 8
        for (int k = 0; k < 128; k++) o += hs[k]*w2r[k];
        out[b*2 + j] = o;
    }
}

// ---------------------------------------------------------------------------
// host launcher
// ---------------------------------------------------------------------------
static float* sym_addr(const void* sym) {
    void* p = nullptr;
    cudaGetSymbolAddress(&p, sym);
    return (float*)p;
}

extern "C" void kernel_launch(void* const* d_in, const int* in_sizes, int n_in,
                              void* d_out, int out_size)
{
    const float* x         = (const float*)d_in[0];
    const float* emb_proto = (const float*)d_in[1];
    const float* emb_flags = (const float*)d_in[2];
    const float* emb_dir   = (const float*)d_in[3];
    const float* plw       = (const float*)d_in[4];
    const float* plb       = (const float*)d_in[5];
    const float* piw       = (const float*)d_in[6];
    const float* pib       = (const float*)d_in[7];
    const float* fusion_w  = (const float*)d_in[8];
    const float* fusion_b  = (const float*)d_in[9];
    const float* tok_g     = (const float*)d_in[10];
    const float* tok_b     = (const float*)d_in[11];
    const float* norm_g    = (const float*)d_in[12];
    const float* norm_b    = (const float*)d_in[13];
    const float* in_proj_w = (const float*)d_in[14];
    const float* conv_w    = (const float*)d_in[15];
    const float* conv_b    = (const float*)d_in[16];
    const float* x_proj_w  = (const float*)d_in[17];
    const float* dt_w      = (const float*)d_in[18];
    const float* dt_b      = (const float*)d_in[19];
    const float* A_log     = (const float*)d_in[20];
    const float* D_param   = (const float*)d_in[21];
    const float* out_proj_w= (const float*)d_in[22];
    const float* cls_w1    = (const float*)d_in[23];
    const float* cls_b1    = (const float*)d_in[24];
    const float* cls_w2    = (const float*)d_in[25];
    const float* cls_b2    = (const float*)d_in[26];

    static float* feat = nullptr;
    static float *xz, *xc, *dbl, *dt, *y, *outb;
    if (!feat) {
        feat = sym_addr(g_feat); xz = sym_addr(g_xz); xc = sym_addr(g_xc);
        dbl = sym_addr(g_dbl);   dt = sym_addr(g_dt); y  = sym_addr(g_y);
        outb = sym_addr(g_out);
    }

    featurize<<<NTOK, DM>>>(x, emb_proto, emb_flags, emb_dir,
                            plw, plb, piw, pib,
                            fusion_w, fusion_b, tok_g, tok_b, feat);

    for (int l = 0; l < NL; l++) {
        gemm_tn<<<dim3((2*DI)/64, NTOK/32), 256>>>(feat, in_proj_w + (size_t)l*2*DI*DM,
                                                   xz, NTOK, 2*DI, DM);
        fused_mid<<<NTOK, DI>>>(xz,
                                conv_w + (size_t)l*DI*4, conv_b + (size_t)l*DI,
                                x_proj_w + (size_t)l*48*DI,
                                dt_w + (size_t)l*DI*DR, dt_b + (size_t)l*DI,
                                xc, dbl, dt);
        scan_kernel<<<(NB*DI)/256, 256>>>(dt, xc, xz, dbl,
                                          A_log + (size_t)l*DI*DS,
                                          D_param + (size_t)l*DI, y);
        gemm_tn<<<dim3(DM/64, NTOK/32), 256>>>(y, out_proj_w + (size_t)l*DM*DI,
                                               outb, NTOK, DM, DI);
        add_ln<<<NTOK, DM>>>(outb, feat, norm_g, norm_b);
    }

    classifier<<<NB, 128>>>(feat, cls_w1, cls_b1, cls_w2, cls_b2, (float*)d_out);
}

// round 2
// speedup vs baseline: 1.4355x; 1.4355x over previous
#include <cuda_runtime.h>
#include <cuda_bf16.h>
#include <math.h>

// B=16, T=32 (early-exit: only token 31 feeds classifier; all ops causal),
// D_MODEL=256, D_INNER=512, D_STATE=16, DT_RANK=16, DCONV=4, L=4.

#define NB      16
#define TT      32
#define NTOK    (NB*TT)      // 512
#define DM      256
#define DI      512
#define DS      16
#define DR      16
#define NL      4

// scratch (device globals; no allocation allowed)
__device__ float g_feat[NTOK*DM];
__device__ float g_xz  [NTOK*2*DI];
__device__ float g_dbl [NTOK*48];
__device__ float g_xct [NB*DI*TT];   // xc transposed [b,d,t]
__device__ float g_ztr [NB*DI*TT];   // z  transposed [b,d,t]
__device__ float g_dtt [NB*DI*TT];   // dt transposed [b,d,t]
__device__ float g_y   [NTOK*DI];
__device__ float g_out [NTOK*DM];

// ---------------------------------------------------------------------------
// Kernel 0: tokenize/fuse/LN -> feat (512 x 256). One block per token.
// ---------------------------------------------------------------------------
__global__ void featurize(const float* __restrict__ x,
                          const float* __restrict__ ep,  const float* __restrict__ ef,
                          const float* __restrict__ ed,
                          const float* __restrict__ plw, const float* __restrict__ plb,
                          const float* __restrict__ piw, const float* __restrict__ pib,
                          const float* __restrict__ fw,  const float* __restrict__ fb,
                          const float* __restrict__ tg,  const float* __restrict__ tb,
                          float* __restrict__ feat)
{
    __shared__ float cat[136];
    __shared__ float red[DM];
    int tok = blockIdx.x;
    int b = tok >> 5, tl = tok & 31;
    const float* xr = x + (b*1024 + tl)*5;   // full seq stride is 1024
    int d = threadIdx.x;
    if (d < 136) {
        float v;
        if (d < 32)       { int p = (int)xr[0]; p = min(max(p,0),255); v = ep[p*32 + d]; }
        else if (d < 64)  { v = xr[1]*plw[d-32] + plb[d-32]; }
        else if (d < 96)  { int f = (int)xr[2]; f = min(max(f,0),63);  v = ef[f*32 + (d-64)]; }
        else if (d < 128) { v = xr[3]*piw[d-96] + pib[d-96]; }
        else              { int dd = (int)xr[4]; dd = min(max(dd,0),1); v = ed[dd*8 + (d-128)]; }
        cat[d] = v;
    }
    __syncthreads();
    float acc = fb[d];
    const float* wrow = fw + d*136;
    #pragma unroll 8
    for (int j = 0; j < 136; j++) acc += cat[j]*wrow[j];
    red[d] = acc; __syncthreads();
    for (int off = 128; off; off >>= 1) { if (d < off) red[d] += red[d+off]; __syncthreads(); }
    float mean = red[0] * (1.f/DM); __syncthreads();
    float dv = acc - mean; red[d] = dv*dv; __syncthreads();
    for (int off = 128; off; off >>= 1) { if (d < off) red[d] += red[d+off]; __syncthreads(); }
    float var = red[0] * (1.f/DM);
    feat[tok*DM + d] = dv * rsqrtf(var + 1e-5f) * tg[d] + tb[d];
}

// ---------------------------------------------------------------------------
// C[M,N] = A[M,K] @ B[N,K]^T.  BM=BN=64, BK=16, 256 thr, 4x4 microtile.
// M,N multiples of 64; K multiple of 16.
// ---------------------------------------------------------------------------
__global__ void gemm_tn(const float* __restrict__ A, const float* __restrict__ B,
                        float* __restrict__ C, int M, int N, int K)
{
    __shared__ __align__(16) float As[16][68];
    __shared__ __align__(16) float Bs[16][68];
    int bm = blockIdx.y*64, bn = blockIdx.x*64;
    int tid = threadIdx.x;
    int lr = tid >> 2;            // 0..63
    int lk = (tid & 3) * 4;       // 0,4,8,12
    int ty = tid >> 4, tx = tid & 15;
    float acc[4][4] = {};
    for (int k0 = 0; k0 < K; k0 += 16) {
        float4 av = *(const float4*)(A + (size_t)(bm+lr)*K + k0 + lk);
        float4 bv = *(const float4*)(B + (size_t)(bn+lr)*K + k0 + lk);
        As[lk+0][lr]=av.x; As[lk+1][lr]=av.y; As[lk+2][lr]=av.z; As[lk+3][lr]=av.w;
        Bs[lk+0][lr]=bv.x; Bs[lk+1][lr]=bv.y; Bs[lk+2][lr]=bv.z; Bs[lk+3][lr]=bv.w;
        __syncthreads();
        #pragma unroll
        for (int k = 0; k < 16; k++) {
            float4 a = *(const float4*)&As[k][ty*4];
            float4 bb = *(const float4*)&Bs[k][tx*4];
            float ar[4] = {a.x,a.y,a.z,a.w};
            float br[4] = {bb.x,bb.y,bb.z,bb.w};
            #pragma unroll
            for (int r = 0; r < 4; r++)
                #pragma unroll
                for (int c = 0; c < 4; c++)
                    acc[r][c] += ar[r]*br[c];
        }
        __syncthreads();
    }
    #pragma unroll
    for (int r = 0; r < 4; r++) {
        float4 o = make_float4(acc[r][0],acc[r][1],acc[r][2],acc[r][3]);
        *(float4*)(C + (size_t)(bm+ty*4+r)*N + bn + tx*4) = o;
    }
}

// ---------------------------------------------------------------------------
// Fused: causal depthwise conv(4)+SiLU -> xc ; xc @ x_proj^T -> dbl(48) ;
// softplus(dtr @ dt_w^T + dt_b) -> dt. Writes xc/z/dt in [b,d,t] layout.
// One block (512 thr) per token.
// ---------------------------------------------------------------------------
__global__ void fused_mid(const float* __restrict__ xz,
                          const float* __restrict__ cw, const float* __restrict__ cb,
                          const float* __restrict__ xpw,
                          const float* __restrict__ dtw, const float* __restrict__ dtb,
                          float* __restrict__ xct, float* __restrict__ ztr,
                          float* __restrict__ dbl, float* __restrict__ dtt)
{
    __shared__ float xcs[DI];
    __shared__ float dbls[48];
    int tok = blockIdx.x;
    int b = tok >> 5, tl = tok & 31;
    int d = threadIdx.x;

    float acc = cb[d];
    #pragma unroll
    for (int k = 0; k < 4; k++) {
        int tt = tl - 3 + k;
        if (tt >= 0) acc += cw[d*4 + k] * xz[(tok - 3 + k)*(2*DI) + d];
    }
    float s = acc / (1.f + __expf(-acc));   // SiLU
    xcs[d] = s;
    int tri = (b*DI + d)*TT + tl;
    xct[tri] = s;
    ztr[tri] = xz[tok*(2*DI) + DI + d];
    __syncthreads();

    int warp = d >> 5, lane = d & 31;
    #pragma unroll
    for (int i = 0; i < 3; i++) {
        int o = warp*3 + i;                 // 16 warps * 3 = 48 outputs
        const float* wr = xpw + o*DI;
        float p = 0.f;
        #pragma unroll
        for (int j = 0; j < DI/32; j++) p += xcs[j*32+lane]*wr[j*32+lane];
        #pragma unroll
        for (int off = 16; off; off >>= 1) p += __shfl_down_sync(0xffffffffu, p, off);
        if (lane == 0) { dbls[o] = p; dbl[tok*48 + o] = p; }
    }
    __syncthreads();

    float v = dtb[d];
    const float* dwr = dtw + d*DR;
    #pragma unroll
    for (int r = 0; r < DR; r++) v += dbls[r]*dwr[r];
    dtt[tri] = (v > 20.f) ? v : log1pf(__expf(v));   // softplus
}

// ---------------------------------------------------------------------------
// Parallel selective scan: one block per (b,d). warp = state n, lane = time t.
// Linear recurrence h_t = a_t h_{t-1} + b_t via Hillis-Steele warp scan.
// exp fast-path: if A[n] == (n+1)*A[0] (checked at runtime), use
// exp(dt*A_n) = exp(dt*A_0)^(n+1); else generic __expf.
// Fuses y = (scan + D*xc) * silu(z).
// ---------------------------------------------------------------------------
__global__ void scan2(const float* __restrict__ dtt, const float* __restrict__ xct,
                      const float* __restrict__ ztr, const float* __restrict__ dbl,
                      const float* __restrict__ A_log, const float* __restrict__ Dp,
                      float* __restrict__ y)
{
    __shared__ float dts[TT], xcs[TT], zs[TT], es[TT];
    __shared__ float Bs[TT][17], Cs[TT][17];
    __shared__ float hc[DS][33];
    __shared__ int   sflag;

    int bd = blockIdx.x;             // b*512 + d
    int b = bd >> 9, d = bd & (DI-1);
    int tid = threadIdx.x;
    int n = tid >> 5, t = tid & 31;

    // per-warp A value (same across lanes)
    float An = -__expf(A_log[d*DS + n]);

    // structure check (warp 0): A[m] == (m+1)*A[0] for all m?
    if (n == 0) {
        float al = -__expf(A_log[d*DS + (t & 15)]);
        float a0 = __shfl_sync(0xffffffffu, al, 0);
        float tgt = (float)((t & 15) + 1) * a0;
        bool ok = fabsf(al - tgt) <= 1e-5f*fabsf(al) + 1e-7f;
        unsigned bal = __ballot_sync(0xffffffffu, ok);
        if (t == 0) sflag = (bal == 0xffffffffu);
    }

    float Dd = 0.f;
    if (tid < TT) {
        int tri = bd*TT + tid;
        float dtv = dtt[tri];
        dts[tid] = dtv;
        xcs[tid] = xct[tri];
        zs[tid]  = ztr[tri];
        Dd = Dp[d];
        float A0 = -__expf(A_log[d*DS]);
        es[tid] = __expf(dtv*A0);
    }
    {   // B/C loads: 512 threads cover 32t x 16n
        int tt2 = tid >> 4, nn = tid & 15;
        const float* row = dbl + ((b*TT + tt2)*48);
        Bs[tt2][nn] = row[16 + nn];
        Cs[tt2][nn] = row[32 + nn];
    }
    __syncthreads();

    float dtv = dts[t];
    float a;
    if (sflag) {
        // a = es[t]^(n+1) by binary exponentiation (uniform per warp)
        float base = es[t], r = 1.f;
        int p = n + 1;
        while (p) { if (p & 1) r *= base; base *= base; p >>= 1; }
        a = r;
    } else {
        a = __expf(dtv*An);
    }
    float bq = dtv * xcs[t] * Bs[t][n];

    // inclusive scan over t within warp: (a,b) composition
    #pragma unroll
    for (int off = 1; off < 32; off <<= 1) {
        float ap = __shfl_up_sync(0xffffffffu, a,  off);
        float bp = __shfl_up_sync(0xffffffffu, bq, off);
        if (t >= off) { bq = bp*a + bq; a = ap*a; }
    }
    // bq == h_t for state n
    hc[n][t] = bq * Cs[t][n];
    __syncthreads();

    if (tid < TT) {
        float sum = 0.f;
        #pragma unroll
        for (int m = 0; m < DS; m++) sum += hc[m][tid];
        float zv = zs[tid];
        float sz = zv / (1.f + __expf(-zv));
        y[((b*TT + tid)*DI) + d] = (sum + Dd*xcs[tid]) * sz;
    }
}

// ---------------------------------------------------------------------------
// residual add + LayerNorm -> feat. One block per token.
// ---------------------------------------------------------------------------
__global__ void add_ln(const float* __restrict__ yo, float* __restrict__ feat,
                       const float* __restrict__ g, const float* __restrict__ b)
{
    __shared__ float red[DM];
    int tok = blockIdx.x, d = threadIdx.x;
    float v = yo[tok*DM + d] + feat[tok*DM + d];
    red[d] = v; __syncthreads();
    for (int off = 128; off; off >>= 1) { if (d < off) red[d] += red[d+off]; __syncthreads(); }
    float mean = red[0] * (1.f/DM); __syncthreads();
    float dv = v - mean; red[d] = dv*dv; __syncthreads();
    for (int off = 128; off; off >>= 1) { if (d < off) red[d] += red[d+off]; __syncthreads(); }
    float var = red[0] * (1.f/DM);
    feat[tok*DM + d] = dv * rsqrtf(var + 1e-5f) * g[d] + b[d];
}

// ---------------------------------------------------------------------------
// Classifier on token 31 of each batch.
// ---------------------------------------------------------------------------
__global__ void classifier(const float* __restrict__ feat,
                           const float* __restrict__ w1, const float* __restrict__ b1,
                           const float* __restrict__ w2, const float* __restrict__ b2,
                           float* __restrict__ out)
{
    __shared__ float hs[128];
    int b = blockIdx.x, j = threadIdx.x;
    const float* fr = feat + (b*TT + 31)*DM;
    float acc = b1[j];
    const float* wr = w1 + j*DM;
    #pragma unroll 8
    for (int d = 0; d < DM; d++) acc += fr[d]*wr[d];
    hs[j] = fmaxf(acc, 0.f);
    __syncthreads();
    if (j < 2) {
        float o = b2[j];
        const float* w2r = w2 + j*128;
        #pragma unroll 8
        for (int k = 0; k < 128; k++) o += hs[k]*w2r[k];
        out[b*2 + j] = o;
    }
}

// ---------------------------------------------------------------------------
static float* sym_addr(const void* sym) {
    void* p = nullptr;
    cudaGetSymbolAddress(&p, sym);
    return (float*)p;
}

extern "C" void kernel_launch(void* const* d_in, const int* in_sizes, int n_in,
                              void* d_out, int out_size)
{
    const float* x         = (const float*)d_in[0];
    const float* emb_proto = (const float*)d_in[1];
    const float* emb_flags = (const float*)d_in[2];
    const float* emb_dir   = (const float*)d_in[3];
    const float* plw       = (const float*)d_in[4];
    const float* plb       = (const float*)d_in[5];
    const float* piw       = (const float*)d_in[6];
    const float* pib       = (const float*)d_in[7];
    const float* fusion_w  = (const float*)d_in[8];
    const float* fusion_b  = (const float*)d_in[9];
    const float* tok_g     = (const float*)d_in[10];
    const float* tok_b     = (const float*)d_in[11];
    const float* norm_g    = (const float*)d_in[12];
    const float* norm_b    = (const float*)d_in[13];
    const float* in_proj_w = (const float*)d_in[14];
    const float* conv_w    = (const float*)d_in[15];
    const float* conv_b    = (const float*)d_in[16];
    const float* x_proj_w  = (const float*)d_in[17];
    const float* dt_w      = (const float*)d_in[18];
    const float* dt_b      = (const float*)d_in[19];
    const float* A_log     = (const float*)d_in[20];
    const float* D_param   = (const float*)d_in[21];
    const float* out_proj_w= (const float*)d_in[22];
    const float* cls_w1    = (const float*)d_in[23];
    const float* cls_b1    = (const float*)d_in[24];
    const float* cls_w2    = (const float*)d_in[25];
    const float* cls_b2    = (const float*)d_in[26];

    static float *feat=nullptr, *xz, *dbl, *xct, *ztr, *dtt, *y, *outb;
    if (!feat) {
        feat = sym_addr(g_feat); xz = sym_addr(g_xz); dbl = sym_addr(g_dbl);
        xct = sym_addr(g_xct);   ztr = sym_addr(g_ztr); dtt = sym_addr(g_dtt);
        y = sym_addr(g_y);       outb = sym_addr(g_out);
    }

    featurize<<<NTOK, DM>>>(x, emb_proto, emb_flags, emb_dir,
                            plw, plb, piw, pib,
                            fusion_w, fusion_b, tok_g, tok_b, feat);

    for (int l = 0; l < NL; l++) {
        gemm_tn<<<dim3((2*DI)/64, NTOK/64), 256>>>(feat, in_proj_w + (size_t)l*2*DI*DM,
                                                   xz, NTOK, 2*DI, DM);
        fused_mid<<<NTOK, DI>>>(xz,
                                conv_w + (size_t)l*DI*4, conv_b + (size_t)l*DI,
                                x_proj_w + (size_t)l*48*DI,
                                dt_w + (size_t)l*DI*DR, dt_b + (size_t)l*DI,
                                xct, ztr, dbl, dtt);
        scan2<<<NB*DI, 512>>>(dtt, xct, ztr, dbl,
                              A_log + (size_t)l*DI*DS,
                              D_param + (size_t)l*DI, y);
        gemm_tn<<<dim3(DM/64, NTOK/64), 256>>>(y, out_proj_w + (size_t)l*DM*DI,
                                               outb, NTOK, DM, DI);
        add_ln<<<NTOK, DM>>>(outb, feat, norm_g, norm_b);
    }

    classifier<<<NB, 128>>>(feat, cls_w1, cls_b1, cls_w2, cls_b2, (float*)d_out);
}

// round 3
// speedup vs baseline: 1.7470x; 1.2170x over previous
#include <cuda_runtime.h>
#include <cuda_bf16.h>
#include <math.h>

// B=16, T=32 (early exit: only token 31 used; all ops causal), DM=256,
// DI=512, DS=16, DR=16, DCONV=4, L=4. Whole net in one persistent kernel.

#define NB      16
#define TT      32
#define NTOK    (NB*TT)      // 512
#define DM      256
#define DI      512
#define DS      16
#define DR      16
#define NL      4
#define THREADS 256
#define SPLIT_IN  2
#define SPLIT_OUT 4

// scratch (device globals; no allocation allowed)
__device__ float g_feat[NTOK*DM];
__device__ float g_xzp [SPLIT_IN][NTOK*2*DI];
__device__ float g_dbl [NTOK*48];
__device__ float g_xct [NB*DI*TT];
__device__ float g_ztr [NB*DI*TT];
__device__ float g_dtt [NB*DI*TT];
__device__ float g_y   [NTOK*DI];
__device__ float g_outp[SPLIT_OUT][NTOK*DM];

__device__ int      g_bar_count;
__device__ unsigned g_bar_phase;

__global__ void reset_bar() { g_bar_count = 0; g_bar_phase = 0u; }

__device__ __forceinline__ void gsync(unsigned& phase) {
    __syncthreads();
    if (threadIdx.x == 0) {
        __threadfence();
        phase += 1u;
        if (atomicAdd(&g_bar_count, 1) == (int)gridDim.x - 1) {
            g_bar_count = 0;
            __threadfence();
            atomicExch(&g_bar_phase, phase);
        } else {
            while (atomicAdd(&g_bar_phase, 0u) < phase) { }
        }
    }
    __syncthreads();
}

// shared scratch: max stage need = scan (3616 floats = 14.4KB)
#define SMTOT 3664

// ---------------------------------------------------------------------------
// 64x64 tile SGEMM piece: C[bm:bm+64, bn:bn+64] (+)= A[.,kbeg:kend] @ B^T
// ---------------------------------------------------------------------------
__device__ __forceinline__ void gemm_tile(const float* __restrict__ A,
                                          const float* __restrict__ B,
                                          float* __restrict__ C,
                                          int N, int K, int bm, int bn,
                                          int kbeg, int kend, float* sm)
{
    float (*As)[68] = (float(*)[68])sm;
    float (*Bs)[68] = (float(*)[68])(sm + 16*68);
    int tid = threadIdx.x;
    int lr = tid >> 2, lk = (tid & 3) * 4;
    int ty = tid >> 4, tx = tid & 15;
    float acc[4][4] = {};
    for (int k0 = kbeg; k0 < kend; k0 += 16) {
        float4 av = *(const float4*)(A + (size_t)(bm+lr)*K + k0 + lk);
        float4 bv = *(const float4*)(B + (size_t)(bn+lr)*K + k0 + lk);
        As[lk+0][lr]=av.x; As[lk+1][lr]=av.y; As[lk+2][lr]=av.z; As[lk+3][lr]=av.w;
        Bs[lk+0][lr]=bv.x; Bs[lk+1][lr]=bv.y; Bs[lk+2][lr]=bv.z; Bs[lk+3][lr]=bv.w;
        __syncthreads();
        #pragma unroll
        for (int k = 0; k < 16; k++) {
            float4 a  = *(const float4*)&As[k][ty*4];
            float4 bb = *(const float4*)&Bs[k][tx*4];
            float ar[4] = {a.x,a.y,a.z,a.w};
            float br[4] = {bb.x,bb.y,bb.z,bb.w};
            #pragma unroll
            for (int r = 0; r < 4; r++)
                #pragma unroll
                for (int c = 0; c < 4; c++)
                    acc[r][c] += ar[r]*br[c];
        }
        __syncthreads();
    }
    #pragma unroll
    for (int r = 0; r < 4; r++)
        *(float4*)(C + (size_t)(bm+ty*4+r)*N + bn + tx*4) =
            make_float4(acc[r][0],acc[r][1],acc[r][2],acc[r][3]);
}

__device__ __forceinline__ void stage_gemm(const float* A, const float* W,
                                           float* Cp, int M, int N, int K,
                                           int S, float* sm)
{
    int ntn = N/64, nt = (M/64)*ntn;
    int ks = K / S;
    for (int w = blockIdx.x; w < nt*S; w += gridDim.x) {
        int s = w / nt, t = w - s*nt;
        int bm = (t / ntn)*64, bn = (t - (t/ntn)*ntn)*64;
        gemm_tile(A, W, Cp + (size_t)s*M*N, N, K, bm, bn, s*ks, s*ks+ks, sm);
    }
}

// ---------------------------------------------------------------------------
__global__ void __launch_bounds__(THREADS, 2)
mega(const float* __restrict__ x,
     const float* __restrict__ ep,  const float* __restrict__ ef,
     const float* __restrict__ ed,
     const float* __restrict__ plw, const float* __restrict__ plb,
     const float* __restrict__ piw, const float* __restrict__ pib,
     const float* __restrict__ fw,  const float* __restrict__ fb,
     const float* __restrict__ tg,  const float* __restrict__ tb,
     const float* __restrict__ ng,  const float* __restrict__ nb,
     const float* __restrict__ ipw, const float* __restrict__ cw,
     const float* __restrict__ cb,  const float* __restrict__ xpw,
     const float* __restrict__ dtw, const float* __restrict__ dtb,
     const float* __restrict__ alog,const float* __restrict__ dp,
     const float* __restrict__ opw,
     const float* __restrict__ w1,  const float* __restrict__ b1,
     const float* __restrict__ w2,  const float* __restrict__ b2,
     float* __restrict__ out)
{
    __shared__ __align__(16) float SMF[SMTOT];
    unsigned phase = 0u;
    const int tid = threadIdx.x;
    const int G = gridDim.x;

    // ---------------- featurize + tok LN -> g_feat -----------------------
    {
        float* cat = SMF;          // 136
        float* red = SMF + 144;    // 256
        for (int tok = blockIdx.x; tok < NTOK; tok += G) {
            int b = tok >> 5, tl = tok & 31;
            const float* xr = x + (b*1024 + tl)*5;
            int d = tid;
            if (d < 136) {
                float v;
                if (d < 32)       { int p=(int)xr[0]; p=min(max(p,0),255); v=ep[p*32+d]; }
                else if (d < 64)  { v = xr[1]*plw[d-32] + plb[d-32]; }
                else if (d < 96)  { int f=(int)xr[2]; f=min(max(f,0),63); v=ef[f*32+(d-64)]; }
                else if (d < 128) { v = xr[3]*piw[d-96] + pib[d-96]; }
                else              { int dd=(int)xr[4]; dd=min(max(dd,0),1); v=ed[dd*8+(d-128)]; }
                cat[d] = v;
            }
            __syncthreads();
            float acc = fb[d];
            const float* wrow = fw + d*136;
            #pragma unroll 8
            for (int j = 0; j < 136; j++) acc += cat[j]*wrow[j];
            red[d] = acc; __syncthreads();
            for (int off=128; off; off>>=1){ if (d<off) red[d]+=red[d+off]; __syncthreads(); }
            float mean = red[0]*(1.f/DM); __syncthreads();
            float dv = acc-mean; red[d]=dv*dv; __syncthreads();
            for (int off=128; off; off>>=1){ if (d<off) red[d]+=red[d+off]; __syncthreads(); }
            float var = red[0]*(1.f/DM);
            g_feat[tok*DM + d] = dv*rsqrtf(var+1e-5f)*tg[d] + tb[d];
            __syncthreads();
        }
    }
    gsync(phase);

    for (int l = 0; l < NL; l++) {
        const float* ipw_l = ipw + (size_t)l*2*DI*DM;
        const float* cw_l  = cw  + (size_t)l*DI*4;
        const float* cb_l  = cb  + (size_t)l*DI;
        const float* xpw_l = xpw + (size_t)l*48*DI;
        const float* dtw_l = dtw + (size_t)l*DI*DR;
        const float* dtb_l = dtb + (size_t)l*DI;
        const float* al_l  = alog+ (size_t)l*DI*DS;
        const float* dp_l  = dp  + (size_t)l*DI;
        const float* opw_l = opw + (size_t)l*DM*DI;

        // -------- in_proj: xz = feat @ ipw^T (split-K=2 partials) --------
        stage_gemm(g_feat, ipw_l, &g_xzp[0][0], NTOK, 2*DI, DM, SPLIT_IN, SMF);
        gsync(phase);

        // -------- conv+SiLU, x_proj, dt (per token) ----------------------
        {
            float* xcs  = SMF;        // 512
            float* dbls = SMF + 512;  // 48
            const float* xz0 = &g_xzp[0][0];
            const float* xz1 = &g_xzp[1][0];
            for (int tok = blockIdx.x; tok < NTOK; tok += G) {
                int b = tok >> 5, tl = tok & 31;
                #pragma unroll
                for (int r = 0; r < 2; r++) {
                    int d = tid + r*256;
                    float acc = cb_l[d];
                    #pragma unroll
                    for (int k = 0; k < 4; k++) {
                        int tt = tl - 3 + k;
                        if (tt >= 0) {
                            int off = (tok-3+k)*(2*DI) + d;
                            acc += cw_l[d*4+k] * (xz0[off] + xz1[off]);
                        }
                    }
                    xcs[d] = acc / (1.f + __expf(-acc));
                }
                __syncthreads();
                int warp = tid >> 5, lane = tid & 31;
                #pragma unroll
                for (int i = 0; i < 6; i++) {
                    int o = warp*6 + i;
                    const float* wr = xpw_l + o*DI;
                    float p = 0.f;
                    #pragma unroll
                    for (int j = 0; j < 16; j++) p += xcs[j*32+lane]*wr[j*32+lane];
                    #pragma unroll
                    for (int off = 16; off; off >>= 1)
                        p += __shfl_down_sync(0xffffffffu, p, off);
                    if (lane == 0) { dbls[o] = p; g_dbl[tok*48 + o] = p; }
                }
                __syncthreads();
                #pragma unroll
                for (int r = 0; r < 2; r++) {
                    int d = tid + r*256;
                    float v = dtb_l[d];
                    const float* dwr = dtw_l + d*DR;
                    #pragma unroll
                    for (int rr = 0; rr < DR; rr++) v += dbls[rr]*dwr[rr];
                    int tri = (b*DI + d)*TT + tl;
                    g_dtt[tri] = (v > 20.f) ? v : log1pf(__expf(v));
                    g_xct[tri] = xcs[d];
                    int zo = tok*2*DI + DI + d;
                    g_ztr[tri] = xz0[zo] + xz1[zo];
                }
                __syncthreads();
            }
        }
        gsync(phase);

        // -------- selective scan: serial t, parallel (d,n) ---------------
        {
            float* Bsm = SMF;            // 512
            float* Csm = SMF + 512;      // 512
            float* ws  = SMF + 1024;     // 512
            float* es  = SMF + 1536;     // 512
            float* xs  = SMF + 2048;     // 512
            float* zs  = SMF + 2560;     // 512
            float* dts = SMF + 3072;     // 512
            float* A0s = SMF + 3584;     // 16
            for (int chunk = blockIdx.x; chunk < NB*32; chunk += G) {
                int b = chunk >> 5;
                int d0 = (chunk & 31) * 16;
                if (tid < 16) A0s[tid] = -__expf(al_l[(d0+tid)*DS]);
                __syncthreads();
                #pragma unroll
                for (int i = tid; i < 512; i += 256) {
                    int t = i >> 4, n = i & 15;
                    const float* row = g_dbl + (b*TT + t)*48;
                    Bsm[t*16+n] = row[16+n];
                    Csm[t*16+n] = row[32+n];
                    int ch = i >> 5, tt = i & 31;
                    int tri = (b*DI + d0 + ch)*TT + tt;
                    float dtv = g_dtt[tri];
                    float xv  = g_xct[tri];
                    dts[ch*32+tt] = dtv;
                    ws [ch*32+tt] = dtv*xv;
                    xs [ch*32+tt] = xv;
                    zs [ch*32+tt] = g_ztr[tri];
                    es [ch*32+tt] = __expf(dtv * A0s[ch]);
                }
                __syncthreads();
                int lane = tid & 31;
                int ch = (tid >> 5)*2 + (lane >> 4);
                int n = lane & 15;
                int d = d0 + ch;
                float An = -__expf(al_l[d*DS + n]);
                float A0 = A0s[ch];
                bool fast = fabsf(An - (float)(n+1)*A0) <= 1e-5f*fabsf(An) + 1e-7f;
                fast = __all_sync(0xffffffffu, fast);
                float Dd = dp_l[d];
                float h = 0.f;
                int np = n + 1;
                if (fast) {
                    #pragma unroll 4
                    for (int t = 0; t < TT; t++) {
                        float e1 = es[ch*32+t];
                        float p2 = e1*e1, p4 = p2*p2, p8 = p4*p4;
                        float a = 1.f;
                        if (np & 1)  a *= e1;
                        if (np & 2)  a *= p2;
                        if (np & 4)  a *= p4;
                        if (np & 8)  a *= p8;
                        if (np & 16) a *= p8*p8;
                        h = a*h + ws[ch*32+t]*Bsm[t*16+n];
                        float v = h*Csm[t*16+n];
                        v += __shfl_xor_sync(0xffffffffu, v, 8);
                        v += __shfl_xor_sync(0xffffffffu, v, 4);
                        v += __shfl_xor_sync(0xffffffffu, v, 2);
                        v += __shfl_xor_sync(0xffffffffu, v, 1);
                        if (n == 0) {
                            float zv = zs[ch*32+t];
                            float sz = zv / (1.f + __expf(-zv));
                            g_y[(b*TT+t)*DI + d] = (v + Dd*xs[ch*32+t]) * sz;
                        }
                    }
                } else {
                    #pragma unroll 4
                    for (int t = 0; t < TT; t++) {
                        float a = __expf(dts[ch*32+t]*An);
                        h = a*h + ws[ch*32+t]*Bsm[t*16+n];
                        float v = h*Csm[t*16+n];
                        v += __shfl_xor_sync(0xffffffffu, v, 8);
                        v += __shfl_xor_sync(0xffffffffu, v, 4);
                        v += __shfl_xor_sync(0xffffffffu, v, 2);
                        v += __shfl_xor_sync(0xffffffffu, v, 1);
                        if (n == 0) {
                            float zv = zs[ch*32+t];
                            float sz = zv / (1.f + __expf(-zv));
                            g_y[(b*TT+t)*DI + d] = (v + Dd*xs[ch*32+t]) * sz;
                        }
                    }
                }
                __syncthreads();
            }
        }
        gsync(phase);

        // -------- out_proj: split-K=4 partials ---------------------------
        stage_gemm(g_y, opw_l, &g_outp[0][0], NTOK, DM, DI, SPLIT_OUT, SMF);
        gsync(phase);

        // -------- residual + LN -> feat ----------------------------------
        {
            float* red = SMF;
            for (int tok = blockIdx.x; tok < NTOK; tok += G) {
                int d = tid;
                int o = tok*DM + d;
                float v = g_feat[o] + g_outp[0][o] + g_outp[1][o]
                                    + g_outp[2][o] + g_outp[3][o];
                red[d] = v; __syncthreads();
                for (int off=128; off; off>>=1){ if (d<off) red[d]+=red[d+off]; __syncthreads(); }
                float mean = red[0]*(1.f/DM); __syncthreads();
                float dv = v-mean; red[d]=dv*dv; __syncthreads();
                for (int off=128; off; off>>=1){ if (d<off) red[d]+=red[d+off]; __syncthreads(); }
                float var = red[0]*(1.f/DM);
                g_feat[o] = dv*rsqrtf(var+1e-5f)*ng[d] + nb[d];
                __syncthreads();
            }
        }
        gsync(phase);
    }

    // ---------------- classifier on token 31 ------------------------------
    if (blockIdx.x < NB) {
        float* hs = SMF;
        int b = blockIdx.x, j = tid;
        const float* fr = g_feat + (b*TT + 31)*DM;
        if (j < 128) {
            float acc = b1[j];
            const float* wr = w1 + j*DM;
            #pragma unroll 8
            for (int d = 0; d < DM; d++) acc += fr[d]*wr[d];
            hs[j] = fmaxf(acc, 0.f);
        }
        __syncthreads();
        if (j < 2) {
            float o = b2[j];
            const float* w2r = w2 + j*128;
            #pragma unroll 8
            for (int k = 0; k < 128; k++) o += hs[k]*w2r[k];
            out[b*2 + j] = o;
        }
    }
}

// ---------------------------------------------------------------------------
extern "C" void kernel_launch(void* const* d_in, const int* in_sizes, int n_in,
                              void* d_out, int out_size)
{
    static int G = 0;
    if (!G) {
        int dev = 0; cudaGetDevice(&dev);
        int nsm = 0; cudaDeviceGetAttribute(&nsm, cudaDevAttrMultiProcessorCount, dev);
        int bpm = 0;
        cudaOccupancyMaxActiveBlocksPerMultiprocessor(&bpm, mega, THREADS, 0);
        if (bpm < 1) bpm = 1;
        if (bpm > 3) bpm = 3;
        G = nsm * bpm;
        if (G < 1) G = 1;
        if (G > 1024) G = 1024;
    }

    reset_bar<<<1,1>>>();
    mega<<<G, THREADS>>>(
        (const float*)d_in[0],  (const float*)d_in[1],  (const float*)d_in[2],
        (const float*)d_in[3],  (const float*)d_in[4],  (const float*)d_in[5],
        (const float*)d_in[6],  (const float*)d_in[7],  (const float*)d_in[8],
        (const float*)d_in[9],  (const float*)d_in[10], (const float*)d_in[11],
        (const float*)d_in[12], (const float*)d_in[13], (const float*)d_in[14],
        (const float*)d_in[15], (const float*)d_in[16], (const float*)d_in[17],
        (const float*)d_in[18], (const float*)d_in[19], (const float*)d_in[20],
        (const float*)d_in[21], (const float*)d_in[22], (const float*)d_in[23],
        (const float*)d_in[24], (const float*)d_in[25], (const float*)d_in[26],
        (float*)d_out);
}